// round 14
// baseline (speedup 1.0000x reference)
#include <cuda_runtime.h>
#include <math.h>

#define BSZ   2
#define CH    256
#define SCTX  1024
#define NH    8
#define HD    32
#define TTOT  8525

typedef unsigned long long ull;

__device__ __forceinline__ void fma2(ull& d, ull a, ull b) {
    asm("fma.rn.f32x2 %0, %1, %2, %0;" : "+l"(d) : "l"(a), "l"(b));
}
__device__ __forceinline__ void mul2(ull& d, ull a) {
    asm("mul.rn.f32x2 %0, %0, %1;" : "+l"(d) : "l"(a));
}
__device__ __forceinline__ ull bcast2(float f) {
    ull d; unsigned u = __float_as_uint(f);
    asm("mov.b64 %0, {%1, %1};" : "=l"(d) : "r"(u));
    return d;
}
__device__ __forceinline__ ull pack2(float lo, float hi) {
    ull d; unsigned a = __float_as_uint(lo), b = __float_as_uint(hi);
    asm("mov.b64 %0, {%1, %2};" : "=l"(d) : "r"(a), "r"(b));
    return d;
}
__device__ __forceinline__ float2 unpack2(ull v) {
    unsigned lo, hi;
    asm("mov.b64 {%0, %1}, %2;" : "=r"(lo), "=r"(hi) : "l"(v));
    return make_float2(__uint_as_float(lo), __uint_as_float(hi));
}

__device__ float g_v    [BSZ * TTOT * CH];
__device__ float g_vn   [BSZ * TTOT * CH];
__device__ float g_q    [BSZ * TTOT * CH];
__device__ float g_cn   [BSZ * SCTX * CH];
__device__ float g_k    [BSZ * SCTX * CH];
__device__ float g_val  [BSZ * SCTX * CH];
__device__ float g_o    [BSZ * TTOT * CH];
__device__ float g_delta[BSZ * TTOT * CH];
__device__ float g_g1   [BSZ * TTOT * (CH / 2)];
__device__ float g_nv   [BSZ * TTOT * CH];
__device__ int   g_sidx [BSZ * SCTX];
__device__ int   g_scnt [BSZ];

// ---------------- merged gather: all 5 levels, p-tiles 200/50/13/4/1 ---------
__global__ void gather_all_kernel(const float* __restrict__ q0, const float* __restrict__ q1,
                                  const float* __restrict__ q2, const float* __restrict__ q3,
                                  const float* __restrict__ q4, float* __restrict__ v)
{
    __shared__ float tile[32][33];
    int bx = blockIdx.x;
    const float* in; int hw, tstart, p0;
    if      (bx < 200) { in = q0; hw = 6400; tstart = 0;    p0 = bx * 32; }
    else if (bx < 250) { in = q1; hw = 1600; tstart = 6400; p0 = (bx - 200) * 32; }
    else if (bx < 263) { in = q2; hw = 400;  tstart = 8000; p0 = (bx - 250) * 32; }
    else if (bx < 267) { in = q3; hw = 100;  tstart = 8400; p0 = (bx - 263) * 32; }
    else               { in = q4; hw = 25;   tstart = 8500; p0 = (bx - 267) * 32; }
    int b = blockIdx.z, ch0 = blockIdx.y * 32;
    int tx = threadIdx.x, ty = threadIdx.y;
#pragma unroll
    for (int i = 0; i < 4; i++) {
        int ch = ch0 + ty + i * 8, p = p0 + tx;
        if (p < hw) tile[ty + i * 8][tx] = in[((size_t)(b * CH + ch)) * hw + p];
    }
    __syncthreads();
#pragma unroll
    for (int i = 0; i < 4; i++) {
        int p = p0 + ty + i * 8, ch = ch0 + tx;
        if (p < hw) v[((size_t)(b * TTOT + tstart + p)) * CH + ch] = tile[tx][ty + i * 8];
    }
}

// ---------------- merged scatter ---------------------------------------------
__global__ void scatter_all_kernel(const float* __restrict__ nv, float* __restrict__ out)
{
    __shared__ float tile[32][33];
    int bx = blockIdx.x;
    int hw, tstart, p0; size_t obase;
    if      (bx < 200) { hw = 6400; tstart = 0;    obase = 0;       p0 = bx * 32; }
    else if (bx < 250) { hw = 1600; tstart = 6400; obase = 3276800; p0 = (bx - 200) * 32; }
    else if (bx < 263) { hw = 400;  tstart = 8000; obase = 4096000; p0 = (bx - 250) * 32; }
    else if (bx < 267) { hw = 100;  tstart = 8400; obase = 4300800; p0 = (bx - 263) * 32; }
    else               { hw = 25;   tstart = 8500; obase = 4352000; p0 = (bx - 267) * 32; }
    int b = blockIdx.z, ch0 = blockIdx.y * 32;
    int tx = threadIdx.x, ty = threadIdx.y;
#pragma unroll
    for (int i = 0; i < 4; i++) {
        int p = p0 + ty + i * 8, ch = ch0 + tx;
        if (p < hw) tile[ty + i * 8][tx] = nv[((size_t)(b * TTOT + tstart + p)) * CH + ch];
    }
    __syncthreads();
#pragma unroll
    for (int i = 0; i < 4; i++) {
        int ch = ch0 + ty + i * 8, p = p0 + tx;
        if (p < hw) out[obase + ((size_t)(b * CH + ch)) * hw + p] = tile[tx][ty + i * 8];
    }
}

__global__ void ln_kernel(const float* __restrict__ x, const float* __restrict__ gg,
                          const float* __restrict__ bb, float* __restrict__ y)
{
    int row = blockIdx.x, tid = threadIdx.x;
    float v = x[(size_t)row * CH + tid];
    float s = v, sq = v * v;
#pragma unroll
    for (int o = 16; o > 0; o >>= 1) {
        s  += __shfl_xor_sync(0xffffffffu, s,  o);
        sq += __shfl_xor_sync(0xffffffffu, sq, o);
    }
    __shared__ float ss[8], ssq[8];
    int w = tid >> 5, l = tid & 31;
    if (l == 0) { ss[w] = s; ssq[w] = sq; }
    __syncthreads();
    if (w == 0) {
        float s2 = ss[l & 7], q2 = ssq[l & 7];
#pragma unroll
        for (int o = 4; o > 0; o >>= 1) {
            s2 += __shfl_xor_sync(0xffffffffu, s2, o);
            q2 += __shfl_xor_sync(0xffffffffu, q2, o);
        }
        if (l == 0) { ss[0] = s2; ssq[0] = q2; }
    }
    __syncthreads();
    float mean = ss[0] * (1.0f / CH);
    float var  = ssq[0] * (1.0f / CH) - mean * mean;
    y[(size_t)row * CH + tid] = (v - mean) * rsqrtf(var + 1e-5f) * gg[tid] + bb[tid];
}

__global__ void compact_kernel(const int* __restrict__ mask, int* __restrict__ sidx,
                               int* __restrict__ scnt)
{
    int b = blockIdx.x, t = threadIdx.x;
    __shared__ int wsum[32];
    int m = mask[b * SCTX + t];
    unsigned bal = __ballot_sync(0xffffffffu, m != 0);
    int lane = t & 31, w = t >> 5;
    if (lane == 0) wsum[w] = __popc(bal);
    __syncthreads();
    if (w == 0) {
        int v = wsum[lane];
#pragma unroll
        for (int o = 1; o < 32; o <<= 1) {
            int n = __shfl_up_sync(0xffffffffu, v, o);
            if (lane >= o) v += n;
        }
        wsum[lane] = v;
    }
    __syncthreads();
    int base = (w == 0) ? 0 : wsum[w - 1];
    int pre  = __popc(bal & ((1u << lane) - 1u));
    if (m) sidx[b * SCTX + base + pre] = t;
    if (t == 0) scnt[b] = wsum[31];
}

// ---------------- GEMM: proven 128x64 block, FFMA2 (R4/R8 version) ----------
#define GBM 128
#define GBN 64
#define GBK 32

template <int EPI>
__global__ void __launch_bounds__(256)
gemm_kernel(const float* __restrict__ A, const float* __restrict__ W,
            const float* __restrict__ bias, float* __restrict__ Cm,
            int M, int N, int K, float scale,
            const float* __restrict__ vres, const float* __restrict__ dres)
{
    __shared__ __align__(16) float Ast[GBK][GBM + 4];
    __shared__ __align__(16) float Bs [GBK][GBN + 4];
    int bm = blockIdx.y * GBM, bn = blockIdx.x * GBN, tid = threadIdx.x;
    int trow = tid >> 4, tcol = tid & 15;
    ull acc2[4][4] = {};
    for (int k0 = 0; k0 < K; k0 += GBK) {
#pragma unroll
        for (int e = 0; e < 4; e++) {
            int lin = tid + e * 256;
            int r = lin >> 3, c4 = (lin & 7) << 2, gr = bm + r;
            float4 av = make_float4(0.f, 0.f, 0.f, 0.f);
            if (gr < M) av = *(const float4*)&A[(size_t)gr * K + k0 + c4];
            Ast[c4 + 0][r] = av.x;
            Ast[c4 + 1][r] = av.y;
            Ast[c4 + 2][r] = av.z;
            Ast[c4 + 3][r] = av.w;
        }
#pragma unroll
        for (int e = 0; e < 2; e++) {
            int lin = tid + e * 256;
            int r = lin >> 4, c4 = (lin & 15) << 2;
            *(float4*)&Bs[r][c4] = *(const float4*)&W[(size_t)(k0 + r) * N + bn + c4];
        }
        __syncthreads();
#pragma unroll
        for (int k = 0; k < GBK; k++) {
            ulonglong2 aL = *(const ulonglong2*)&Ast[k][trow * 8];
            ulonglong2 aH = *(const ulonglong2*)&Ast[k][trow * 8 + 4];
            float4 bv = *(const float4*)&Bs[k][tcol * 4];
            ull b0 = bcast2(bv.x), b1 = bcast2(bv.y);
            ull b2 = bcast2(bv.z), b3 = bcast2(bv.w);
            fma2(acc2[0][0], aL.x, b0); fma2(acc2[0][1], aL.x, b1);
            fma2(acc2[0][2], aL.x, b2); fma2(acc2[0][3], aL.x, b3);
            fma2(acc2[1][0], aL.y, b0); fma2(acc2[1][1], aL.y, b1);
            fma2(acc2[1][2], aL.y, b2); fma2(acc2[1][3], aL.y, b3);
            fma2(acc2[2][0], aH.x, b0); fma2(acc2[2][1], aH.x, b1);
            fma2(acc2[2][2], aH.x, b2); fma2(acc2[2][3], aH.x, b3);
            fma2(acc2[3][0], aH.y, b0); fma2(acc2[3][1], aH.y, b1);
            fma2(acc2[3][2], aH.y, b2); fma2(acc2[3][3], aH.y, b3);
        }
        __syncthreads();
    }
    float4 bb = *(const float4*)&bias[bn + tcol * 4];
#pragma unroll
    for (int rp = 0; rp < 4; rp++) {
        float2 c0 = unpack2(acc2[rp][0]);
        float2 c1 = unpack2(acc2[rp][1]);
        float2 c2 = unpack2(acc2[rp][2]);
        float2 c3 = unpack2(acc2[rp][3]);
        float rowv[2][4] = {{c0.x, c1.x, c2.x, c3.x},
                            {c0.y, c1.y, c2.y, c3.y}};
#pragma unroll
        for (int hh = 0; hh < 2; hh++) {
            int gr = bm + trow * 8 + rp * 2 + hh;
            if (gr >= M) continue;
            float vv[4] = {rowv[hh][0] + bb.x, rowv[hh][1] + bb.y,
                           rowv[hh][2] + bb.z, rowv[hh][3] + bb.w};
#pragma unroll
            for (int j = 0; j < 4; j++) {
                int gc = bn + tcol * 4 + j;
                float val = vv[j];
                if (EPI == 1) val *= scale;
                if (EPI == 2) val = fmaxf(val, 0.0f);
                if (EPI == 3) {
                    size_t ridx = (size_t)gr * 256 + gc;
                    val = vres[ridx] + tanhf(val) * dres[ridx];
                }
                vv[j] = val;
            }
            *(float4*)&Cm[(size_t)gr * N + bn + tcol * 4] =
                make_float4(vv[0], vv[1], vv[2], vv[3]);
        }
    }
}

// ---------------- flash attention: AQ=128, AS=64, 2-part PV (4 dims/thread) --
#define AQ 128
#define AS 64
#define ATTN_SMEM_FLOATS 17536
#define ATTN_SMEM_BYTES  (ATTN_SMEM_FLOATS * 4)

__global__ void __launch_bounds__(256, 2)
attn_kernel(const float* __restrict__ Qb, const float* __restrict__ Kb,
            const float* __restrict__ Vb, const int* __restrict__ sidxp,
            const int* __restrict__ scnt, float* __restrict__ Ob)
{
    extern __shared__ __align__(16) float sm[];
    float* Qst    = sm;            // [k][row] stride 132 (also merge buffer at end)
    float* Kst    = sm + 4224;     // [k][s]   stride 68
    float* Vs     = sm + 6400;     // [s][d]   stride 36
    float* Lst    = sm + 8704;     // [s][row] stride 132
    float* rowm   = sm + 17152;
    float* rowl   = sm + 17280;
    float* rowfac = sm + 17408;

    int b = blockIdx.z, h = blockIdx.y, t0 = blockIdx.x * AQ, tid = threadIdx.x;
    int trow = tid >> 4, tcol = tid & 15;          // QK indexing
    int part = tid >> 7, rowg = (tid >> 3) & 15, dimg = tid & 7;  // PV indexing
    int cnt = scnt[b];

    if (tid < AQ) { rowm[tid] = -INFINITY; rowl[tid] = 0.0f; }

#pragma unroll
    for (int e = 0; e < 4; e++) {
        int lin = tid + e * 256;
        int r = lin >> 3, c4 = (lin & 7) << 2, t = t0 + r;
        float4 qv = make_float4(0.f, 0.f, 0.f, 0.f);
        if (t < TTOT) qv = *(const float4*)&Qb[((size_t)(b * TTOT + t)) * CH + h * HD + c4];
        Qst[(c4 + 0) * 132 + r] = qv.x;
        Qst[(c4 + 1) * 132 + r] = qv.y;
        Qst[(c4 + 2) * 132 + r] = qv.z;
        Qst[(c4 + 3) * 132 + r] = qv.w;
    }

    ull acc2[4][4] = {};   // [row-pair][dim j], dims dimg*4..+3, s-partitioned

    for (int s0 = 0; s0 < cnt; s0 += AS) {
        int rem = cnt - s0;
        __syncthreads();
#pragma unroll
        for (int e = 0; e < 2; e++) {
            int lin = tid + e * 256;
            int sr = lin >> 3, c4 = (lin & 7) << 2;
            int sidx = (sr < rem) ? sidxp[b * SCTX + s0 + sr] : 0;
            size_t gbase = ((size_t)(b * SCTX + sidx)) * CH + h * HD + c4;
            float4 kv = *(const float4*)&Kb[gbase];
            float4 vv = *(const float4*)&Vb[gbase];
            Kst[(c4 + 0) * 68 + sr] = kv.x;
            Kst[(c4 + 1) * 68 + sr] = kv.y;
            Kst[(c4 + 2) * 68 + sr] = kv.z;
            Kst[(c4 + 3) * 68 + sr] = kv.w;
            *(float4*)&Vs[sr * 36 + c4] = vv;
        }
        __syncthreads();

        // QK logits: 8x4 micro-tile per thread, packed row pairs
        ull lg2[4][4] = {};
#pragma unroll
        for (int k = 0; k < HD; k++) {
            ulonglong2 aL = *(const ulonglong2*)&Qst[k * 132 + trow * 8];
            ulonglong2 aH = *(const ulonglong2*)&Qst[k * 132 + trow * 8 + 4];
            float4 kv = *(const float4*)&Kst[k * 68 + tcol * 4];
            ull b0 = bcast2(kv.x), b1 = bcast2(kv.y);
            ull b2 = bcast2(kv.z), b3 = bcast2(kv.w);
            fma2(lg2[0][0], aL.x, b0); fma2(lg2[0][1], aL.x, b1);
            fma2(lg2[0][2], aL.x, b2); fma2(lg2[0][3], aL.x, b3);
            fma2(lg2[1][0], aL.y, b0); fma2(lg2[1][1], aL.y, b1);
            fma2(lg2[1][2], aL.y, b2); fma2(lg2[1][3], aL.y, b3);
            fma2(lg2[2][0], aH.x, b0); fma2(lg2[2][1], aH.x, b1);
            fma2(lg2[2][2], aH.x, b2); fma2(lg2[2][3], aH.x, b3);
            fma2(lg2[3][0], aH.y, b0); fma2(lg2[3][1], aH.y, b1);
            fma2(lg2[3][2], aH.y, b2); fma2(lg2[3][3], aH.y, b3);
        }
#pragma unroll
        for (int j = 0; j < 4; j++) {
            float mj = (s0 + tcol * 4 + j < cnt) ? 1.0f : -9e15f;
            ulonglong2 stL, stH;
            {
                float2 c = unpack2(lg2[0][j]);
                c.x = fminf(fmaxf(c.x, -50000.0f), 50000.0f) + mj;
                c.y = fminf(fmaxf(c.y, -50000.0f), 50000.0f) + mj;
                stL.x = pack2(c.x, c.y);
            }
            {
                float2 c = unpack2(lg2[1][j]);
                c.x = fminf(fmaxf(c.x, -50000.0f), 50000.0f) + mj;
                c.y = fminf(fmaxf(c.y, -50000.0f), 50000.0f) + mj;
                stL.y = pack2(c.x, c.y);
            }
            {
                float2 c = unpack2(lg2[2][j]);
                c.x = fminf(fmaxf(c.x, -50000.0f), 50000.0f) + mj;
                c.y = fminf(fmaxf(c.y, -50000.0f), 50000.0f) + mj;
                stH.x = pack2(c.x, c.y);
            }
            {
                float2 c = unpack2(lg2[3][j]);
                c.x = fminf(fmaxf(c.x, -50000.0f), 50000.0f) + mj;
                c.y = fminf(fmaxf(c.y, -50000.0f), 50000.0f) + mj;
                stH.y = pack2(c.x, c.y);
            }
            int sIdx = tcol * 4 + j;
            *(ulonglong2*)&Lst[sIdx * 132 + trow * 8]     = stL;
            *(ulonglong2*)&Lst[sIdx * 132 + trow * 8 + 4] = stH;
        }
        __syncthreads();

        // online softmax: 2 threads per row
        {
            int r = tid >> 1, half = tid & 1;
            float v[32];
#pragma unroll
            for (int q = 0; q < 32; q++)
                v[q] = Lst[(half * 32 + q) * 132 + r];
            float mold = rowm[r];
            float cmax = -INFINITY;
#pragma unroll
            for (int j = 0; j < 32; j++) cmax = fmaxf(cmax, v[j]);
            cmax = fmaxf(cmax, __shfl_xor_sync(0xffffffffu, cmax, 1));
            float newm = fmaxf(mold, cmax);
            float csum = 0.0f;
#pragma unroll
            for (int j = 0; j < 32; j++) {
                v[j] = __expf(v[j] - newm);
                csum += v[j];
            }
#pragma unroll
            for (int q = 0; q < 32; q++)
                Lst[(half * 32 + q) * 132 + r] = v[q];
            csum += __shfl_xor_sync(0xffffffffu, csum, 1);
            float fac = __expf(mold - newm);
            if (half == 0) {
                rowfac[r] = fac;
                rowl[r]   = rowl[r] * fac + csum;
                rowm[r]   = newm;
            }
        }
        __syncthreads();

        // PV: 2 s-partitions, each thread 8 rows x 4 dims
        {
#pragma unroll
            for (int rp = 0; rp < 4; rp++) {
                ull fp = *(const ull*)&rowfac[rowg * 8 + rp * 2];
                mul2(acc2[rp][0], fp); mul2(acc2[rp][1], fp);
                mul2(acc2[rp][2], fp); mul2(acc2[rp][3], fp);
            }
            int sbeg = part * 32;
#pragma unroll 4
            for (int ss = 0; ss < 32; ss++) {
                int s = sbeg + ss;
                ulonglong2 pL = *(const ulonglong2*)&Lst[s * 132 + rowg * 8];
                ulonglong2 pH = *(const ulonglong2*)&Lst[s * 132 + rowg * 8 + 4];
                float4 v4 = *(const float4*)&Vs[s * 36 + dimg * 4];
                ull vb0 = bcast2(v4.x), vb1 = bcast2(v4.y);
                ull vb2 = bcast2(v4.z), vb3 = bcast2(v4.w);
                fma2(acc2[0][0], pL.x, vb0); fma2(acc2[0][1], pL.x, vb1);
                fma2(acc2[0][2], pL.x, vb2); fma2(acc2[0][3], pL.x, vb3);
                fma2(acc2[1][0], pL.y, vb0); fma2(acc2[1][1], pL.y, vb1);
                fma2(acc2[1][2], pL.y, vb2); fma2(acc2[1][3], pL.y, vb3);
                fma2(acc2[2][0], pH.x, vb0); fma2(acc2[2][1], pH.x, vb1);
                fma2(acc2[2][2], pH.x, vb2); fma2(acc2[2][3], pH.x, vb3);
                fma2(acc2[3][0], pH.y, vb0); fma2(acc2[3][1], pH.y, vb1);
                fma2(acc2[3][2], pH.y, vb2); fma2(acc2[3][3], pH.y, vb3);
            }
        }
    }

    // merge the two s-partitions through smem (reuse Qst area: 128*32=4096 floats)
    __syncthreads();
    if (part == 1) {
#pragma unroll
        for (int rp = 0; rp < 4; rp++) {
            float2 c0 = unpack2(acc2[rp][0]);
            float2 c1 = unpack2(acc2[rp][1]);
            float2 c2 = unpack2(acc2[rp][2]);
            float2 c3 = unpack2(acc2[rp][3]);
            int r0 = rowg * 8 + rp * 2;
            *(float4*)&sm[(r0 + 0) * 32 + dimg * 4] = make_float4(c0.x, c1.x, c2.x, c3.x);
            *(float4*)&sm[(r0 + 1) * 32 + dimg * 4] = make_float4(c0.y, c1.y, c2.y, c3.y);
        }
    }
    __syncthreads();
    if (part == 0) {
#pragma unroll
        for (int rp = 0; rp < 4; rp++) {
            float2 c0 = unpack2(acc2[rp][0]);
            float2 c1 = unpack2(acc2[rp][1]);
            float2 c2 = unpack2(acc2[rp][2]);
            float2 c3 = unpack2(acc2[rp][3]);
#pragma unroll
            for (int hh = 0; hh < 2; hh++) {
                int row = rowg * 8 + rp * 2 + hh;
                int t = t0 + row;
                if (t >= TTOT) continue;
                float inv = 1.0f / rowl[row];
                float4 m4 = *(const float4*)&sm[row * 32 + dimg * 4];
                float4 o4;
                o4.x = ((hh ? c0.y : c0.x) + m4.x) * inv;
                o4.y = ((hh ? c1.y : c1.x) + m4.y) * inv;
                o4.z = ((hh ? c2.y : c2.x) + m4.z) * inv;
                o4.w = ((hh ? c3.y : c3.x) + m4.w) * inv;
                *(float4*)&Ob[((size_t)(b * TTOT + t)) * CH + h * HD + dimg * 4] = o4;
            }
        }
    }
}

// ---------------- launch ------------------------------------------------------
extern "C" void kernel_launch(void* const* d_in, const int* in_sizes, int n_in,
                              void* d_out, int out_size)
{
    const float* qin[5];
    for (int i = 0; i < 5; i++) qin[i] = (const float*)d_in[i];
    const float* cache  = (const float*)d_in[5];
    const int*   mask   = (const int*)d_in[6];
    const float* ln_v_g = (const float*)d_in[7];
    const float* ln_v_b = (const float*)d_in[8];
    const float* ln_c_g = (const float*)d_in[9];
    const float* ln_c_b = (const float*)d_in[10];
    const float* Wv  = (const float*)d_in[11];
    const float* bv  = (const float*)d_in[12];
    const float* Wc  = (const float*)d_in[13];
    const float* bc  = (const float*)d_in[14];
    const float* Wvc = (const float*)d_in[15];
    const float* bvc = (const float*)d_in[16];
    const float* Wo  = (const float*)d_in[17];
    const float* bo  = (const float*)d_in[18];
    const float* Wg1 = (const float*)d_in[19];
    const float* bg1 = (const float*)d_in[20];
    const float* Wg2 = (const float*)d_in[21];
    const float* bg2 = (const float*)d_in[22];
    float* out = (float*)d_out;

    float *pv, *pvn, *pq, *pcn, *pk, *pval, *po, *pdelta, *pg1, *pnv;
    int *psidx, *pscnt;
    cudaGetSymbolAddress((void**)&pv,     g_v);
    cudaGetSymbolAddress((void**)&pvn,    g_vn);
    cudaGetSymbolAddress((void**)&pq,     g_q);
    cudaGetSymbolAddress((void**)&pcn,    g_cn);
    cudaGetSymbolAddress((void**)&pk,     g_k);
    cudaGetSymbolAddress((void**)&pval,   g_val);
    cudaGetSymbolAddress((void**)&po,     g_o);
    cudaGetSymbolAddress((void**)&pdelta, g_delta);
    cudaGetSymbolAddress((void**)&pg1,    g_g1);
    cudaGetSymbolAddress((void**)&pnv,    g_nv);
    cudaGetSymbolAddress((void**)&psidx,  g_sidx);
    cudaGetSymbolAddress((void**)&pscnt,  g_scnt);

    cudaFuncSetAttribute(attn_kernel,
                         cudaFuncAttributeMaxDynamicSharedMemorySize, ATTN_SMEM_BYTES);

    const int MROWS = BSZ * TTOT;               // 17050
    const int CROWS = BSZ * SCTX;               // 2048
    const float scale = 0.1767766952966369f;    // 32^-0.5

    dim3 tb(32, 8);
    dim3 gg(268, CH / 32, BSZ);                 // 268 p-tiles across 5 levels

    dim3 gq(CH / GBN, (MROWS + GBM - 1) / GBM); // (4, 134)
    dim3 gc(CH / GBN, CROWS / GBM);             // (4, 16)

    // ncu profiles my launch idx 3 (2 harness pre-launches + -s 5) -> put Wv GEMM there
    gather_all_kernel<<<gg, tb>>>(qin[0], qin[1], qin[2], qin[3], qin[4], pv);  // 0
    compact_kernel<<<BSZ, 1024>>>(mask, psidx, pscnt);                           // 1
    ln_kernel<<<MROWS, 256>>>(pv, ln_v_g, ln_v_b, pvn);                          // 2
    gemm_kernel<1><<<gq, 256>>>(pvn, Wv, bv, pq, MROWS, CH, CH, scale, nullptr, nullptr); // 3 <- profiled
    ln_kernel<<<CROWS, 256>>>(cache, ln_c_g, ln_c_b, pcn);                       // 4
    gemm_kernel<0><<<gc, 256>>>(pcn, Wc,  bc,  pk,   CROWS, CH, CH, 1.0f, nullptr, nullptr); // 5
    gemm_kernel<0><<<gc, 256>>>(pcn, Wvc, bvc, pval, CROWS, CH, CH, 1.0f, nullptr, nullptr); // 6

    dim3 ga((TTOT + AQ - 1) / AQ, NH, BSZ);     // (67, 8, 2)
    attn_kernel<<<ga, 256, ATTN_SMEM_BYTES>>>(pq, pk, pval, psidx, pscnt, po);   // 7

    gemm_kernel<0><<<gq, 256>>>(po, Wo, bo, pdelta, MROWS, CH, CH, 1.0f, nullptr, nullptr); // 8

    dim3 gg1(CH / 2 / GBN, (MROWS + GBM - 1) / GBM);  // (2, 134)
    gemm_kernel<2><<<gg1, 256>>>(pv, Wg1, bg1, pg1, MROWS, CH / 2, CH, 1.0f, nullptr, nullptr); // 9
    gemm_kernel<3><<<gq, 256>>>(pg1, Wg2, bg2, pnv, MROWS, CH, CH / 2, 1.0f, pv, pdelta);       // 10

    scatter_all_kernel<<<gg, tb>>>(pnv, out);                                    // 11
}

// round 16
// speedup vs baseline: 1.5802x; 1.5802x over previous
#include <cuda_runtime.h>
#include <math.h>

#define BSZ   2
#define CH    256
#define SCTX  1024
#define NH    8
#define HD    32
#define TTOT  8525

typedef unsigned long long ull;

__device__ __forceinline__ void fma2(ull& d, ull a, ull b) {
    asm("fma.rn.f32x2 %0, %1, %2, %0;" : "+l"(d) : "l"(a), "l"(b));
}
__device__ __forceinline__ void mul2(ull& d, ull a) {
    asm("mul.rn.f32x2 %0, %0, %1;" : "+l"(d) : "l"(a));
}
__device__ __forceinline__ ull bcast2(float f) {
    ull d; unsigned u = __float_as_uint(f);
    asm("mov.b64 %0, {%1, %1};" : "=l"(d) : "r"(u));
    return d;
}
__device__ __forceinline__ ull pack2(float lo, float hi) {
    ull d; unsigned a = __float_as_uint(lo), b = __float_as_uint(hi);
    asm("mov.b64 %0, {%1, %2};" : "=l"(d) : "r"(a), "r"(b));
    return d;
}
__device__ __forceinline__ float2 unpack2(ull v) {
    unsigned lo, hi;
    asm("mov.b64 {%0, %1}, %2;" : "=r"(lo), "=r"(hi) : "l"(v));
    return make_float2(__uint_as_float(lo), __uint_as_float(hi));
}

__device__ float g_v    [BSZ * TTOT * CH];
__device__ float g_vn   [BSZ * TTOT * CH];
__device__ float g_q    [BSZ * TTOT * CH];
__device__ float g_cn   [BSZ * SCTX * CH];
__device__ float g_k    [BSZ * SCTX * CH];
__device__ float g_val  [BSZ * SCTX * CH];
__device__ float g_o    [BSZ * TTOT * CH];
__device__ float g_delta[BSZ * TTOT * CH];
__device__ float g_g1   [BSZ * TTOT * (CH / 2)];
__device__ float g_nv   [BSZ * TTOT * CH];
__device__ int   g_sidx [BSZ * SCTX];
__device__ int   g_scnt [BSZ];

// ---------------- merged gather: all 5 levels, p-tiles 200/50/13/4/1 ---------
__global__ void gather_all_kernel(const float* __restrict__ q0, const float* __restrict__ q1,
                                  const float* __restrict__ q2, const float* __restrict__ q3,
                                  const float* __restrict__ q4, float* __restrict__ v)
{
    __shared__ float tile[32][33];
    int bx = blockIdx.x;
    const float* in; int hw, tstart, p0;
    if      (bx < 200) { in = q0; hw = 6400; tstart = 0;    p0 = bx * 32; }
    else if (bx < 250) { in = q1; hw = 1600; tstart = 6400; p0 = (bx - 200) * 32; }
    else if (bx < 263) { in = q2; hw = 400;  tstart = 8000; p0 = (bx - 250) * 32; }
    else if (bx < 267) { in = q3; hw = 100;  tstart = 8400; p0 = (bx - 263) * 32; }
    else               { in = q4; hw = 25;   tstart = 8500; p0 = (bx - 267) * 32; }
    int b = blockIdx.z, ch0 = blockIdx.y * 32;
    int tx = threadIdx.x, ty = threadIdx.y;
#pragma unroll
    for (int i = 0; i < 4; i++) {
        int ch = ch0 + ty + i * 8, p = p0 + tx;
        if (p < hw) tile[ty + i * 8][tx] = in[((size_t)(b * CH + ch)) * hw + p];
    }
    __syncthreads();
#pragma unroll
    for (int i = 0; i < 4; i++) {
        int p = p0 + ty + i * 8, ch = ch0 + tx;
        if (p < hw) v[((size_t)(b * TTOT + tstart + p)) * CH + ch] = tile[tx][ty + i * 8];
    }
}

// ---------------- merged scatter ---------------------------------------------
__global__ void scatter_all_kernel(const float* __restrict__ nv, float* __restrict__ out)
{
    __shared__ float tile[32][33];
    int bx = blockIdx.x;
    int hw, tstart, p0; size_t obase;
    if      (bx < 200) { hw = 6400; tstart = 0;    obase = 0;       p0 = bx * 32; }
    else if (bx < 250) { hw = 1600; tstart = 6400; obase = 3276800; p0 = (bx - 200) * 32; }
    else if (bx < 263) { hw = 400;  tstart = 8000; obase = 4096000; p0 = (bx - 250) * 32; }
    else if (bx < 267) { hw = 100;  tstart = 8400; obase = 4300800; p0 = (bx - 263) * 32; }
    else               { hw = 25;   tstart = 8500; obase = 4352000; p0 = (bx - 267) * 32; }
    int b = blockIdx.z, ch0 = blockIdx.y * 32;
    int tx = threadIdx.x, ty = threadIdx.y;
#pragma unroll
    for (int i = 0; i < 4; i++) {
        int p = p0 + ty + i * 8, ch = ch0 + tx;
        if (p < hw) tile[ty + i * 8][tx] = nv[((size_t)(b * TTOT + tstart + p)) * CH + ch];
    }
    __syncthreads();
#pragma unroll
    for (int i = 0; i < 4; i++) {
        int ch = ch0 + ty + i * 8, p = p0 + tx;
        if (p < hw) out[obase + ((size_t)(b * CH + ch)) * hw + p] = tile[tx][ty + i * 8];
    }
}

__global__ void ln_kernel(const float* __restrict__ x, const float* __restrict__ gg,
                          const float* __restrict__ bb, float* __restrict__ y)
{
    int row = blockIdx.x, tid = threadIdx.x;
    float v = x[(size_t)row * CH + tid];
    float s = v, sq = v * v;
#pragma unroll
    for (int o = 16; o > 0; o >>= 1) {
        s  += __shfl_xor_sync(0xffffffffu, s,  o);
        sq += __shfl_xor_sync(0xffffffffu, sq, o);
    }
    __shared__ float ss[8], ssq[8];
    int w = tid >> 5, l = tid & 31;
    if (l == 0) { ss[w] = s; ssq[w] = sq; }
    __syncthreads();
    if (w == 0) {
        float s2 = ss[l & 7], q2 = ssq[l & 7];
#pragma unroll
        for (int o = 4; o > 0; o >>= 1) {
            s2 += __shfl_xor_sync(0xffffffffu, s2, o);
            q2 += __shfl_xor_sync(0xffffffffu, q2, o);
        }
        if (l == 0) { ss[0] = s2; ssq[0] = q2; }
    }
    __syncthreads();
    float mean = ss[0] * (1.0f / CH);
    float var  = ssq[0] * (1.0f / CH) - mean * mean;
    y[(size_t)row * CH + tid] = (v - mean) * rsqrtf(var + 1e-5f) * gg[tid] + bb[tid];
}

__global__ void compact_kernel(const int* __restrict__ mask, int* __restrict__ sidx,
                               int* __restrict__ scnt)
{
    int b = blockIdx.x, t = threadIdx.x;
    __shared__ int wsum[32];
    int m = mask[b * SCTX + t];
    unsigned bal = __ballot_sync(0xffffffffu, m != 0);
    int lane = t & 31, w = t >> 5;
    if (lane == 0) wsum[w] = __popc(bal);
    __syncthreads();
    if (w == 0) {
        int v = wsum[lane];
#pragma unroll
        for (int o = 1; o < 32; o <<= 1) {
            int n = __shfl_up_sync(0xffffffffu, v, o);
            if (lane >= o) v += n;
        }
        wsum[lane] = v;
    }
    __syncthreads();
    int base = (w == 0) ? 0 : wsum[w - 1];
    int pre  = __popc(bal & ((1u << lane) - 1u));
    if (m) sidx[b * SCTX + base + pre] = t;
    if (t == 0) scnt[b] = wsum[31];
}

// ------- GEMM: 128x64 block, FFMA2, double-buffered smem pipeline ------------
#define GBM 128
#define GBN 64
#define GBK 32

template <int EPI>
__global__ void __launch_bounds__(256)
gemm_kernel(const float* __restrict__ A, const float* __restrict__ W,
            const float* __restrict__ bias, float* __restrict__ Cm,
            int M, int N, int K, float scale,
            const float* __restrict__ vres, const float* __restrict__ dres)
{
    __shared__ __align__(16) float Ast[2][GBK][GBM + 4];
    __shared__ __align__(16) float Bs [2][GBK][GBN + 4];
    int bm = blockIdx.y * GBM, bn = blockIdx.x * GBN, tid = threadIdx.x;
    int trow = tid >> 4, tcol = tid & 15;
    // per-thread staging for prefetch
    int ar = tid >> 3, ac4 = (tid & 7) << 2;          // A: rows ar, ar+32, ar+64, ar+96
    int br = tid >> 4, bc4 = (tid & 15) << 2;         // B: rows br, br+16
    float4 pa[4], pb[2];

    // prefetch tile 0
#pragma unroll
    for (int e = 0; e < 4; e++) {
        int gr = bm + ar + e * 32;
        pa[e] = make_float4(0.f, 0.f, 0.f, 0.f);
        if (gr < M) pa[e] = *(const float4*)&A[(size_t)gr * K + ac4];
    }
#pragma unroll
    for (int e = 0; e < 2; e++)
        pb[e] = *(const float4*)&W[(size_t)(br + e * 16) * N + bn + bc4];
    // store tile 0 to buffer 0
#pragma unroll
    for (int e = 0; e < 4; e++) {
        int r = ar + e * 32;
        Ast[0][ac4 + 0][r] = pa[e].x;
        Ast[0][ac4 + 1][r] = pa[e].y;
        Ast[0][ac4 + 2][r] = pa[e].z;
        Ast[0][ac4 + 3][r] = pa[e].w;
    }
#pragma unroll
    for (int e = 0; e < 2; e++)
        *(float4*)&Bs[0][br + e * 16][bc4] = pb[e];
    __syncthreads();

    ull acc2[4][4] = {};
    int niter = K / GBK;
    for (int it = 0; it < niter; it++) {
        int cur = it & 1;
        // prefetch next tile (LDG latency overlapped with compute below)
        if (it + 1 < niter) {
            int k0 = (it + 1) * GBK;
#pragma unroll
            for (int e = 0; e < 4; e++) {
                int gr = bm + ar + e * 32;
                pa[e] = make_float4(0.f, 0.f, 0.f, 0.f);
                if (gr < M) pa[e] = *(const float4*)&A[(size_t)gr * K + k0 + ac4];
            }
#pragma unroll
            for (int e = 0; e < 2; e++)
                pb[e] = *(const float4*)&W[(size_t)(k0 + br + e * 16) * N + bn + bc4];
        }
        // compute on current buffer
#pragma unroll
        for (int k = 0; k < GBK; k++) {
            ulonglong2 aL = *(const ulonglong2*)&Ast[cur][k][trow * 8];
            ulonglong2 aH = *(const ulonglong2*)&Ast[cur][k][trow * 8 + 4];
            float4 bv = *(const float4*)&Bs[cur][k][tcol * 4];
            ull b0 = bcast2(bv.x), b1 = bcast2(bv.y);
            ull b2 = bcast2(bv.z), b3 = bcast2(bv.w);
            fma2(acc2[0][0], aL.x, b0); fma2(acc2[0][1], aL.x, b1);
            fma2(acc2[0][2], aL.x, b2); fma2(acc2[0][3], aL.x, b3);
            fma2(acc2[1][0], aL.y, b0); fma2(acc2[1][1], aL.y, b1);
            fma2(acc2[1][2], aL.y, b2); fma2(acc2[1][3], aL.y, b3);
            fma2(acc2[2][0], aH.x, b0); fma2(acc2[2][1], aH.x, b1);
            fma2(acc2[2][2], aH.x, b2); fma2(acc2[2][3], aH.x, b3);
            fma2(acc2[3][0], aH.y, b0); fma2(acc2[3][1], aH.y, b1);
            fma2(acc2[3][2], aH.y, b2); fma2(acc2[3][3], aH.y, b3);
        }
        // store next tile into alternate buffer (its consumers synced at it-1)
        if (it + 1 < niter) {
            int nxt = cur ^ 1;
#pragma unroll
            for (int e = 0; e < 4; e++) {
                int r = ar + e * 32;
                Ast[nxt][ac4 + 0][r] = pa[e].x;
                Ast[nxt][ac4 + 1][r] = pa[e].y;
                Ast[nxt][ac4 + 2][r] = pa[e].z;
                Ast[nxt][ac4 + 3][r] = pa[e].w;
            }
#pragma unroll
            for (int e = 0; e < 2; e++)
                *(float4*)&Bs[nxt][br + e * 16][bc4] = pb[e];
            __syncthreads();
        }
    }
    float4 bb = *(const float4*)&bias[bn + tcol * 4];
#pragma unroll
    for (int rp = 0; rp < 4; rp++) {
        float2 c0 = unpack2(acc2[rp][0]);
        float2 c1 = unpack2(acc2[rp][1]);
        float2 c2 = unpack2(acc2[rp][2]);
        float2 c3 = unpack2(acc2[rp][3]);
        float rowv[2][4] = {{c0.x, c1.x, c2.x, c3.x},
                            {c0.y, c1.y, c2.y, c3.y}};
#pragma unroll
        for (int hh = 0; hh < 2; hh++) {
            int gr = bm + trow * 8 + rp * 2 + hh;
            if (gr >= M) continue;
            float vv[4] = {rowv[hh][0] + bb.x, rowv[hh][1] + bb.y,
                           rowv[hh][2] + bb.z, rowv[hh][3] + bb.w};
#pragma unroll
            for (int j = 0; j < 4; j++) {
                int gc = bn + tcol * 4 + j;
                float val = vv[j];
                if (EPI == 1) val *= scale;
                if (EPI == 2) val = fmaxf(val, 0.0f);
                if (EPI == 3) {
                    size_t ridx = (size_t)gr * 256 + gc;
                    val = vres[ridx] + tanhf(val) * dres[ridx];
                }
                vv[j] = val;
            }
            *(float4*)&Cm[(size_t)gr * N + bn + tcol * 4] =
                make_float4(vv[0], vv[1], vv[2], vv[3]);
        }
    }
}

// ---------------- flash attention (exact R8 proven version) ------------------
#define AQ 128
#define AS 64
#define ATTN_SMEM_FLOATS 17536
#define ATTN_SMEM_BYTES  (ATTN_SMEM_FLOATS * 4)

__global__ void __launch_bounds__(256)
attn_kernel(const float* __restrict__ Qb, const float* __restrict__ Kb,
            const float* __restrict__ Vb, const int* __restrict__ sidxp,
            const int* __restrict__ scnt, float* __restrict__ Ob)
{
    extern __shared__ __align__(16) float sm[];
    float* Qst    = sm;            // [k][row] stride 132
    float* Kst    = sm + 4224;     // [k][s]   stride 68
    float* Vs     = sm + 6400;     // [s][d]   stride 36
    float* Lst    = sm + 8704;     // [s][row] stride 132
    float* rowm   = sm + 17152;
    float* rowl   = sm + 17280;
    float* rowfac = sm + 17408;

    int b = blockIdx.z, h = blockIdx.y, t0 = blockIdx.x * AQ, tid = threadIdx.x;
    int trow = tid >> 4, tcol = tid & 15;
    int cnt = scnt[b];

    if (tid < AQ) { rowm[tid] = -INFINITY; rowl[tid] = 0.0f; }

#pragma unroll
    for (int e = 0; e < 4; e++) {
        int lin = tid + e * 256;
        int r = lin >> 3, c4 = (lin & 7) << 2, t = t0 + r;
        float4 qv = make_float4(0.f, 0.f, 0.f, 0.f);
        if (t < TTOT) qv = *(const float4*)&Qb[((size_t)(b * TTOT + t)) * CH + h * HD + c4];
        Qst[(c4 + 0) * 132 + r] = qv.x;
        Qst[(c4 + 1) * 132 + r] = qv.y;
        Qst[(c4 + 2) * 132 + r] = qv.z;
        Qst[(c4 + 3) * 132 + r] = qv.w;
    }

    ull acc2[4][2] = {};

    for (int s0 = 0; s0 < cnt; s0 += AS) {
        int rem = cnt - s0;
        __syncthreads();
#pragma unroll
        for (int e = 0; e < 2; e++) {
            int lin = tid + e * 256;
            int sr = lin >> 3, c4 = (lin & 7) << 2;
            int sidx = (sr < rem) ? sidxp[b * SCTX + s0 + sr] : 0;
            size_t gbase = ((size_t)(b * SCTX + sidx)) * CH + h * HD + c4;
            float4 kv = *(const float4*)&Kb[gbase];
            float4 vv = *(const float4*)&Vb[gbase];
            Kst[(c4 + 0) * 68 + sr] = kv.x;
            Kst[(c4 + 1) * 68 + sr] = kv.y;
            Kst[(c4 + 2) * 68 + sr] = kv.z;
            Kst[(c4 + 3) * 68 + sr] = kv.w;
            *(float4*)&Vs[sr * 36 + c4] = vv;
        }
        __syncthreads();

        ull lg2[4][4] = {};
#pragma unroll
        for (int k = 0; k < HD; k++) {
            ulonglong2 aL = *(const ulonglong2*)&Qst[k * 132 + trow * 8];
            ulonglong2 aH = *(const ulonglong2*)&Qst[k * 132 + trow * 8 + 4];
            float4 kv = *(const float4*)&Kst[k * 68 + tcol * 4];
            ull b0 = bcast2(kv.x), b1 = bcast2(kv.y);
            ull b2 = bcast2(kv.z), b3 = bcast2(kv.w);
            fma2(lg2[0][0], aL.x, b0); fma2(lg2[0][1], aL.x, b1);
            fma2(lg2[0][2], aL.x, b2); fma2(lg2[0][3], aL.x, b3);
            fma2(lg2[1][0], aL.y, b0); fma2(lg2[1][1], aL.y, b1);
            fma2(lg2[1][2], aL.y, b2); fma2(lg2[1][3], aL.y, b3);
            fma2(lg2[2][0], aH.x, b0); fma2(lg2[2][1], aH.x, b1);
            fma2(lg2[2][2], aH.x, b2); fma2(lg2[2][3], aH.x, b3);
            fma2(lg2[3][0], aH.y, b0); fma2(lg2[3][1], aH.y, b1);
            fma2(lg2[3][2], aH.y, b2); fma2(lg2[3][3], aH.y, b3);
        }
#pragma unroll
        for (int j = 0; j < 4; j++) {
            float mj = (s0 + tcol * 4 + j < cnt) ? 1.0f : -9e15f;
            ulonglong2 stL, stH;
            {
                float2 c = unpack2(lg2[0][j]);
                c.x = fminf(fmaxf(c.x, -50000.0f), 50000.0f) + mj;
                c.y = fminf(fmaxf(c.y, -50000.0f), 50000.0f) + mj;
                stL.x = pack2(c.x, c.y);
            }
            {
                float2 c = unpack2(lg2[1][j]);
                c.x = fminf(fmaxf(c.x, -50000.0f), 50000.0f) + mj;
                c.y = fminf(fmaxf(c.y, -50000.0f), 50000.0f) + mj;
                stL.y = pack2(c.x, c.y);
            }
            {
                float2 c = unpack2(lg2[2][j]);
                c.x = fminf(fmaxf(c.x, -50000.0f), 50000.0f) + mj;
                c.y = fminf(fmaxf(c.y, -50000.0f), 50000.0f) + mj;
                stH.x = pack2(c.x, c.y);
            }
            {
                float2 c = unpack2(lg2[3][j]);
                c.x = fminf(fmaxf(c.x, -50000.0f), 50000.0f) + mj;
                c.y = fminf(fmaxf(c.y, -50000.0f), 50000.0f) + mj;
                stH.y = pack2(c.x, c.y);
            }
            int sIdx = tcol * 4 + j;
            *(ulonglong2*)&Lst[sIdx * 132 + trow * 8]     = stL;
            *(ulonglong2*)&Lst[sIdx * 132 + trow * 8 + 4] = stH;
        }
        __syncthreads();

        {
            int r = tid >> 1, half = tid & 1;
            float v[32];
#pragma unroll
            for (int q = 0; q < 32; q++)
                v[q] = Lst[(half * 32 + q) * 132 + r];
            float mold = rowm[r];
            float cmax = -INFINITY;
#pragma unroll
            for (int j = 0; j < 32; j++) cmax = fmaxf(cmax, v[j]);
            cmax = fmaxf(cmax, __shfl_xor_sync(0xffffffffu, cmax, 1));
            float newm = fmaxf(mold, cmax);
            float csum = 0.0f;
#pragma unroll
            for (int j = 0; j < 32; j++) {
                v[j] = __expf(v[j] - newm);
                csum += v[j];
            }
#pragma unroll
            for (int q = 0; q < 32; q++)
                Lst[(half * 32 + q) * 132 + r] = v[q];
            csum += __shfl_xor_sync(0xffffffffu, csum, 1);
            float fac = __expf(mold - newm);
            if (half == 0) {
                rowfac[r] = fac;
                rowl[r]   = rowl[r] * fac + csum;
                rowm[r]   = newm;
            }
        }
        __syncthreads();

        {
#pragma unroll
            for (int rp = 0; rp < 4; rp++) {
                ull fpair = *(const ull*)&rowfac[trow * 8 + rp * 2];
                mul2(acc2[rp][0], fpair);
                mul2(acc2[rp][1], fpair);
            }
#pragma unroll 8
            for (int s = 0; s < AS; s++) {
                ulonglong2 pL = *(const ulonglong2*)&Lst[s * 132 + trow * 8];
                ulonglong2 pH = *(const ulonglong2*)&Lst[s * 132 + trow * 8 + 4];
                float2 v2 = *(const float2*)&Vs[s * 36 + tcol * 2];
                ull vb0 = bcast2(v2.x), vb1 = bcast2(v2.y);
                fma2(acc2[0][0], pL.x, vb0); fma2(acc2[0][1], pL.x, vb1);
                fma2(acc2[1][0], pL.y, vb0); fma2(acc2[1][1], pL.y, vb1);
                fma2(acc2[2][0], pH.x, vb0); fma2(acc2[2][1], pH.x, vb1);
                fma2(acc2[3][0], pH.y, vb0); fma2(acc2[3][1], pH.y, vb1);
            }
        }
    }

#pragma unroll
    for (int rp = 0; rp < 4; rp++) {
        float2 d0 = unpack2(acc2[rp][0]);
        float2 d1 = unpack2(acc2[rp][1]);
        int rowA = trow * 8 + rp * 2;
        int tA = t0 + rowA, tB = tA + 1;
        if (tA < TTOT) {
            float inv = 1.0f / rowl[rowA];
            *(float2*)&Ob[((size_t)(b * TTOT + tA)) * CH + h * HD + tcol * 2] =
                make_float2(d0.x * inv, d1.x * inv);
        }
        if (tB < TTOT) {
            float inv = 1.0f / rowl[rowA + 1];
            *(float2*)&Ob[((size_t)(b * TTOT + tB)) * CH + h * HD + tcol * 2] =
                make_float2(d0.y * inv, d1.y * inv);
        }
    }
}

// ---------------- launch ------------------------------------------------------
extern "C" void kernel_launch(void* const* d_in, const int* in_sizes, int n_in,
                              void* d_out, int out_size)
{
    const float* qin[5];
    for (int i = 0; i < 5; i++) qin[i] = (const float*)d_in[i];
    const float* cache  = (const float*)d_in[5];
    const int*   mask   = (const int*)d_in[6];
    const float* ln_v_g = (const float*)d_in[7];
    const float* ln_v_b = (const float*)d_in[8];
    const float* ln_c_g = (const float*)d_in[9];
    const float* ln_c_b = (const float*)d_in[10];
    const float* Wv  = (const float*)d_in[11];
    const float* bv  = (const float*)d_in[12];
    const float* Wc  = (const float*)d_in[13];
    const float* bc  = (const float*)d_in[14];
    const float* Wvc = (const float*)d_in[15];
    const float* bvc = (const float*)d_in[16];
    const float* Wo  = (const float*)d_in[17];
    const float* bo  = (const float*)d_in[18];
    const float* Wg1 = (const float*)d_in[19];
    const float* bg1 = (const float*)d_in[20];
    const float* Wg2 = (const float*)d_in[21];
    const float* bg2 = (const float*)d_in[22];
    float* out = (float*)d_out;

    float *pv, *pvn, *pq, *pcn, *pk, *pval, *po, *pdelta, *pg1, *pnv;
    int *psidx, *pscnt;
    cudaGetSymbolAddress((void**)&pv,     g_v);
    cudaGetSymbolAddress((void**)&pvn,    g_vn);
    cudaGetSymbolAddress((void**)&pq,     g_q);
    cudaGetSymbolAddress((void**)&pcn,    g_cn);
    cudaGetSymbolAddress((void**)&pk,     g_k);
    cudaGetSymbolAddress((void**)&pval,   g_val);
    cudaGetSymbolAddress((void**)&po,     g_o);
    cudaGetSymbolAddress((void**)&pdelta, g_delta);
    cudaGetSymbolAddress((void**)&pg1,    g_g1);
    cudaGetSymbolAddress((void**)&pnv,    g_nv);
    cudaGetSymbolAddress((void**)&psidx,  g_sidx);
    cudaGetSymbolAddress((void**)&pscnt,  g_scnt);

    cudaFuncSetAttribute(attn_kernel,
                         cudaFuncAttributeMaxDynamicSharedMemorySize, ATTN_SMEM_BYTES);

    const int MROWS = BSZ * TTOT;               // 17050
    const int CROWS = BSZ * SCTX;               // 2048
    const float scale = 0.1767766952966369f;    // 32^-0.5

    dim3 tb(32, 8);
    dim3 gg(268, CH / 32, BSZ);                 // 268 p-tiles across 5 levels

    dim3 gq(CH / GBN, (MROWS + GBM - 1) / GBM); // (4, 134)
    dim3 gc(CH / GBN, CROWS / GBM);             // (4, 16)

    // ncu profiles my launch idx 3 -> keep Wv GEMM there to verify pipeline prediction
    gather_all_kernel<<<gg, tb>>>(qin[0], qin[1], qin[2], qin[3], qin[4], pv);  // 0
    compact_kernel<<<BSZ, 1024>>>(mask, psidx, pscnt);                           // 1
    ln_kernel<<<MROWS, 256>>>(pv, ln_v_g, ln_v_b, pvn);                          // 2
    gemm_kernel<1><<<gq, 256>>>(pvn, Wv, bv, pq, MROWS, CH, CH, scale, nullptr, nullptr); // 3 <- profiled
    ln_kernel<<<CROWS, 256>>>(cache, ln_c_g, ln_c_b, pcn);                       // 4
    gemm_kernel<0><<<gc, 256>>>(pcn, Wc,  bc,  pk,   CROWS, CH, CH, 1.0f, nullptr, nullptr); // 5
    gemm_kernel<0><<<gc, 256>>>(pcn, Wvc, bvc, pval, CROWS, CH, CH, 1.0f, nullptr, nullptr); // 6

    dim3 ga((TTOT + AQ - 1) / AQ, NH, BSZ);     // (67, 8, 2)
    attn_kernel<<<ga, 256, ATTN_SMEM_BYTES>>>(pq, pk, pval, psidx, pscnt, po);   // 7

    gemm_kernel<0><<<gq, 256>>>(po, Wo, bo, pdelta, MROWS, CH, CH, 1.0f, nullptr, nullptr); // 8

    dim3 gg1(CH / 2 / GBN, (MROWS + GBM - 1) / GBM);  // (2, 134)
    gemm_kernel<2><<<gg1, 256>>>(pv, Wg1, bg1, pg1, MROWS, CH / 2, CH, 1.0f, nullptr, nullptr); // 9
    gemm_kernel<3><<<gq, 256>>>(pg1, Wg2, bg2, pnv, MROWS, CH, CH / 2, 1.0f, pv, pdelta);       // 10

    scatter_all_kernel<<<gg, tb>>>(pnv, out);                                    // 11
}